// round 1
// baseline (speedup 1.0000x reference)
#include <cuda_runtime.h>
#include <cuda_bf16.h>
#include <cstdint>

// Chamfer distance, 2 x 16384 x 3 fp32 points -> scalar.
// d(a,b)^2 = |a|^2 + (|b|^2 - 2 a.b). Targets preprocessed in smem as
// float4 {-2bx, -2by, -2bz, |b|^2} so inner loop is 3 FFMA + 1 FMNMX per pair.

#define NPTS    16384
#define THREADS 256
#define QPT     4                    // queries per thread (register-resident)
#define QTILE   (THREADS * QPT)      // 1024 queries per block
#define QBLKS   (NPTS / QTILE)       // 16
#define SLICES  8                    // target-set split for parallelism
#define TTILE   (NPTS / SLICES)      // 2048 targets per slice (32KB smem)

// Scratch: per-query running min (uint-reinterpreted non-negative float).
__device__ unsigned int g_min[2 * NPTS];

__global__ void cd_init_kernel() {
    int i = blockIdx.x * blockDim.x + threadIdx.x;
    if (i < 2 * NPTS) g_min[i] = 0x7F800000u;  // +inf
}

__global__ __launch_bounds__(THREADS)
void cd_main_kernel(const float* __restrict__ gt, const float* __restrict__ gen) {
    __shared__ float4 sb[TTILE];

    const int dir = blockIdx.z;                 // 0: gt->gen, 1: gen->gt
    const float* __restrict__ qpts = dir ? gen : gt;
    const float* __restrict__ tpts = dir ? gt : gen;

    // Cooperative load + preprocess of this block's target slice.
    const int tbase = blockIdx.y * TTILE;
    for (int j = threadIdx.x; j < TTILE; j += THREADS) {
        const float* p = tpts + 3 * (tbase + j);
        float x = p[0], y = p[1], z = p[2];
        sb[j] = make_float4(-2.0f * x, -2.0f * y, -2.0f * z,
                            x * x + y * y + z * z);
    }
    __syncthreads();

    // Register-resident queries.
    float ax[QPT], ay[QPT], az[QPT], an[QPT], m[QPT];
    const int q0 = blockIdx.x * QTILE + threadIdx.x;
#pragma unroll
    for (int q = 0; q < QPT; q++) {
        const float* p = qpts + 3 * (q0 + q * THREADS);
        ax[q] = p[0]; ay[q] = p[1]; az[q] = p[2];
        an[q] = ax[q] * ax[q] + ay[q] * ay[q] + az[q] * az[q];
        m[q]  = 3.4e38f;
    }

    // Main loop: per j, one broadcast LDS.128 then 3 FFMA + 1 FMNMX per query.
#pragma unroll 4
    for (int j = 0; j < TTILE; j++) {
        float4 b = sb[j];
#pragma unroll
        for (int q = 0; q < QPT; q++) {
            float d = fmaf(az[q], b.z, fmaf(ay[q], b.y, fmaf(ax[q], b.x, b.w)));
            m[q] = fminf(m[q], d);
        }
    }

    // Fold in |a|^2, clamp tiny negative fp noise, publish via uint atomicMin
    // (valid float ordering for non-negative values).
#pragma unroll
    for (int q = 0; q < QPT; q++) {
        float d = fmaxf(m[q] + an[q], 0.0f);
        atomicMin(&g_min[dir * NPTS + q0 + q * THREADS], __float_as_uint(d));
    }
}

__global__ void cd_reduce_kernel(float* __restrict__ out) {
    __shared__ float ssum[THREADS];
    float s = 0.0f;
    for (int i = threadIdx.x; i < 2 * NPTS; i += THREADS)
        s += __uint_as_float(g_min[i]);
    ssum[threadIdx.x] = s;
    __syncthreads();
    for (int st = THREADS / 2; st > 0; st >>= 1) {
        if (threadIdx.x < st) ssum[threadIdx.x] += ssum[threadIdx.x + st];
        __syncthreads();
    }
    if (threadIdx.x == 0)
        out[0] = ssum[0] / (float)NPTS;  // mean1 + mean2, both over NPTS
}

extern "C" void kernel_launch(void* const* d_in, const int* in_sizes, int n_in,
                              void* d_out, int out_size) {
    const float* gt  = (const float*)d_in[0];
    const float* gen = (const float*)d_in[1];
    float* out = (float*)d_out;

    cd_init_kernel<<<(2 * NPTS + 255) / 256, 256>>>();
    cd_main_kernel<<<dim3(QBLKS, SLICES, 2), THREADS>>>(gt, gen);
    cd_reduce_kernel<<<1, THREADS>>>(out);
}

// round 2
// speedup vs baseline: 1.2755x; 1.2755x over previous
#include <cuda_runtime.h>
#include <cuda_bf16.h>
#include <cstdint>

// Chamfer distance, 2 x 16384 x 3 fp32 -> scalar.
// d(a,b)^2 = |a|^2 + (|b|^2 - 2 a.b). Targets preprocessed + PAIR-PACKED in
// smem as f32x2 lanes {-2bx01, -2by01, -2bz01, |b|^2_01}; query components
// broadcast-packed (a,a) once per thread. Inner step: 3 FFMA2 + 2 FMNMX
// covers 2 query-target pairs (halves the fma-pipe instruction count).

#define NPTS    16384
#define THREADS 256
#define QPT     4                    // queries per thread (register-resident)
#define QTILE   (THREADS * QPT)      // 1024 queries per block
#define QBLKS   (NPTS / QTILE)       // 16
#define SLICES  32                   // target-set split (wave balance: 1024 CTAs)
#define TTILE   (NPTS / SLICES)      // 512 targets per slice
#define TPAIRS  (TTILE / 2)          // 256 packed target pairs (8KB smem)

typedef unsigned long long u64;

__device__ __forceinline__ u64 pack2(float lo, float hi) {
    u64 r; asm("mov.b64 %0, {%1, %2};" : "=l"(r) : "f"(lo), "f"(hi)); return r;
}
__device__ __forceinline__ u64 fma2(u64 a, u64 b, u64 c) {
    u64 r; asm("fma.rn.f32x2 %0, %1, %2, %3;" : "=l"(r) : "l"(a), "l"(b), "l"(c));
    return r;
}
__device__ __forceinline__ void unpack2(u64 v, float& lo, float& hi) {
    asm("mov.b64 {%0, %1}, %2;" : "=f"(lo), "=f"(hi) : "l"(v));
}

// Scratch: per-query running min (uint-reinterpreted non-negative float).
__device__ unsigned int g_min[2 * NPTS];

__global__ void cd_init_kernel() {
    int i = blockIdx.x * blockDim.x + threadIdx.x;
    if (i < 2 * NPTS) g_min[i] = 0x7F800000u;  // +inf
}

__global__ __launch_bounds__(THREADS)
void cd_main_kernel(const float* __restrict__ gt, const float* __restrict__ gen) {
    // Packed target slice: sbA[jp] = {-2bx01, -2by01}, sbB[jp] = {-2bz01, |b|^2_01}
    __shared__ ulonglong2 sbA[TPAIRS];
    __shared__ ulonglong2 sbB[TPAIRS];

    const int dir = blockIdx.z;                 // 0: gt->gen, 1: gen->gt
    const float* __restrict__ qpts = dir ? gen : gt;
    const float* __restrict__ tpts = dir ? gt : gen;

    // Cooperative load + preprocess: one packed target pair per thread.
    const int tbase = blockIdx.y * TTILE;
    {
        int jp = threadIdx.x;                   // THREADS == TPAIRS
        const float* p = tpts + 3 * (tbase + 2 * jp);
        float x0 = p[0], y0 = p[1], z0 = p[2];
        float x1 = p[3], y1 = p[4], z1 = p[5];
        ulonglong2 A, B;
        A.x = pack2(-2.0f * x0, -2.0f * x1);
        A.y = pack2(-2.0f * y0, -2.0f * y1);
        B.x = pack2(-2.0f * z0, -2.0f * z1);
        B.y = pack2(x0 * x0 + y0 * y0 + z0 * z0,
                    x1 * x1 + y1 * y1 + z1 * z1);
        sbA[jp] = A;
        sbB[jp] = B;
    }
    __syncthreads();

    // Register-resident queries, components broadcast-packed (a,a).
    u64 axp[QPT], ayp[QPT], azp[QPT];
    float an[QPT], m[QPT];
    const int q0 = blockIdx.x * QTILE + threadIdx.x;
#pragma unroll
    for (int q = 0; q < QPT; q++) {
        const float* p = qpts + 3 * (q0 + q * THREADS);
        float x = p[0], y = p[1], z = p[2];
        axp[q] = pack2(x, x);
        ayp[q] = pack2(y, y);
        azp[q] = pack2(z, z);
        an[q]  = x * x + y * y + z * z;
        m[q]   = 3.4e38f;
    }

    // Main loop: per packed pair, 2x broadcast LDS.128, then per query
    // 3 FFMA2 + 2 FMNMX covering two target points.
#pragma unroll 4
    for (int jp = 0; jp < TPAIRS; jp++) {
        ulonglong2 A = sbA[jp];
        ulonglong2 B = sbB[jp];
#pragma unroll
        for (int q = 0; q < QPT; q++) {
            u64 d = fma2(axp[q], A.x, fma2(ayp[q], A.y, fma2(azp[q], B.x, B.y)));
            float dlo, dhi;
            unpack2(d, dlo, dhi);
            m[q] = fminf(m[q], fminf(dlo, dhi));
        }
    }

    // Fold in |a|^2, clamp fp noise, publish via uint atomicMin
    // (valid float ordering for non-negative values).
#pragma unroll
    for (int q = 0; q < QPT; q++) {
        float d = fmaxf(m[q] + an[q], 0.0f);
        atomicMin(&g_min[dir * NPTS + q0 + q * THREADS], __float_as_uint(d));
    }
}

__global__ void cd_reduce_kernel(float* __restrict__ out) {
    __shared__ float ssum[THREADS];
    float s = 0.0f;
    for (int i = threadIdx.x; i < 2 * NPTS; i += THREADS)
        s += __uint_as_float(g_min[i]);
    ssum[threadIdx.x] = s;
    __syncthreads();
    for (int st = THREADS / 2; st > 0; st >>= 1) {
        if (threadIdx.x < st) ssum[threadIdx.x] += ssum[threadIdx.x + st];
        __syncthreads();
    }
    if (threadIdx.x == 0)
        out[0] = ssum[0] / (float)NPTS;  // mean1 + mean2, both over NPTS
}

extern "C" void kernel_launch(void* const* d_in, const int* in_sizes, int n_in,
                              void* d_out, int out_size) {
    const float* gt  = (const float*)d_in[0];
    const float* gen = (const float*)d_in[1];
    float* out = (float*)d_out;

    cd_init_kernel<<<(2 * NPTS + 255) / 256, 256>>>();
    cd_main_kernel<<<dim3(QBLKS, SLICES, 2), THREADS>>>(gt, gen);
    cd_reduce_kernel<<<1, THREADS>>>(out);
}